// round 14
// baseline (speedup 1.0000x reference)
#include <cuda_runtime.h>
#include <cstdint>

// PatchEmbed permute: x[16,64,256,256] f32 -> out[16, 64*64, 64*4*4]
// out[n, wp, hp, c, pi, pj] = x[n, c, hp*4+pi, wp*4+pj]
// pj (4 floats) => float4 units. Per (n, hp): transpose M[cp=256][wp=64]
// of float4 where cp = c*4+pi.
//   input  f4 idx = ((n*64 + c)*256 + hp*4 + pi)*64 + wp   (contiguous in wp)
//   output f4 idx = ((n*64 + wp)*64 + hp)*256 + cp          (contiguous in cp)
//
// R14: identical to the best-measured R8/R13 config (256 thr, 16KB tile,
// 64 warps/SM) except the output phase uses sm_10x 256-bit stores
// (st.global.v8.f32): each thread writes one 32B chunk (cp pair), halving
// store wavefronts through L1TEX and LTS request count. Pair-granular
// swizzle col = wp ^ ((cpl>>1)&7):
//   load  (cpl fixed/warp, wp consecutive): distinct col mod 8 -> CF
//   store (8-lane phase: cpq=0..7, wp fixed): banks 4*(wp^cpq) distinct -> CF
//   (2nd LDS.128 row is +1024B = same bank pattern, also CF)

#define N_ 16
#define C_ 64
#define HP_ 64
#define WP_ 64
#define CP_ 256            // C_*4
#define CPT_ 16            // cp rows per tile
#define THREADS 256
#define NDATA    (N_ * C_ * 256 * 256)     // data size in floats

__global__ __launch_bounds__(THREADS, 8)
void patch_permute_kernel(const float4* __restrict__ in, float4* __restrict__ out,
                          int tail_count) {
    __shared__ float4 tile[CPT_][WP_];   // 16 KB, pair-swizzled

    const int cpt = blockIdx.x;    // 0..15  (cp in [cpt*16, cpt*16+16))
    const int hp  = blockIdx.y;    // 0..63
    const int n   = blockIdx.z;    // 0..15
    const int tid = threadIdx.x;

    // ---- fused tail write (ori_shape = 16,64,256,256), one block only ----
    if (cpt == 0 && hp == 0 && n == 0 && tid < 4 && tid < tail_count) {
        const float vals[4] = {16.0f, 64.0f, 256.0f, 256.0f};
        ((float*)out)[NDATA + tid] = vals[tid];
    }

    // ---- load: coalesced over wp (512B per warp), swizzled smem store ----
#pragma unroll
    for (int i = 0; i < (CPT_ * WP_) / THREADS; i++) {   // 4 iters
        int idx = i * THREADS + tid;
        int cpl = idx >> 6;          // 0..15
        int wp  = idx & 63;          // 0..63
        int cp  = cpt * CPT_ + cpl;
        int c   = cp >> 2;
        int pi  = cp & 3;
        int in_idx = ((n * C_ + c) * 256 + hp * 4 + pi) * WP_ + wp;
        tile[cpl][wp ^ ((cpl >> 1) & 7)] = in[in_idx];
    }
    __syncthreads();

    // ---- store: 256-bit STG, 1KB per warp request, swizzled smem reads ----
#pragma unroll
    for (int i = 0; i < (CPT_ * WP_) / (2 * THREADS); i++) {   // 2 iters
        int idx = i * THREADS + tid;
        int wp  = idx >> 3;          // 0..63
        int cpq = idx & 7;           // 0..7 (cp pair)
        int cpl = cpq << 1;          // even cp row
        int col = wp ^ (cpq & 7);    // (cpl>>1)&7 == cpq
        float4 lo = tile[cpl][col];
        float4 hi = tile[cpl + 1][col];
        int cp  = cpt * CPT_ + cpl;
        float* p = (float*)&out[((n * WP_ + wp) * HP_ + hp) * CP_ + cp];
        asm volatile(
            "st.global.v8.f32 [%0], {%1,%2,%3,%4,%5,%6,%7,%8};"
            :: "l"(p),
               "f"(lo.x), "f"(lo.y), "f"(lo.z), "f"(lo.w),
               "f"(hi.x), "f"(hi.y), "f"(hi.z), "f"(hi.w)
            : "memory");
    }
}

extern "C" void kernel_launch(void* const* d_in, const int* in_sizes, int n_in,
                              void* d_out, int out_size) {
    (void)in_sizes; (void)n_in;
    const float4* in  = (const float4*)d_in[0];
    float4*       out = (float4*)d_out;

    int tail_count = out_size > NDATA ? (out_size - NDATA) : 0;

    dim3 grid(CP_ / CPT_, HP_, N_);   // 16 x 64 x 16 = 16384 blocks
    patch_permute_kernel<<<grid, THREADS>>>(in, out, tail_count);
}

// round 15
// speedup vs baseline: 1.0039x; 1.0039x over previous
#include <cuda_runtime.h>
#include <cstdint>

// PatchEmbed permute: x[16,64,256,256] f32 -> out[16, 64*64, 64*4*4]
// out[n, wp, hp, c, pi, pj] = x[n, c, hp*4+pi, wp*4+pj]
// pj (4 floats) => float4 units. Per (n, hp): transpose M[cp=256][wp=64]
// of float4 where cp = c*4+pi.
//   input  f4 idx = ((n*64 + c)*256 + hp*4 + pi)*64 + wp   (contiguous in wp)
//   output f4 idx = ((n*64 + wp)*64 + hp)*256 + cp          (contiguous in cp)
//
// FINAL: 256 threads, 16KB XOR-swizzled smem tile, plain LDG.128/STG.128,
// __launch_bounds__(256,8) -> 8 blocks x 8 warps = 64 warps/SM.
// Best measured: kernel 74.8us = 536.9MB / 74.8us = 7.2 TB/s ~= 90% of the
// 8 TB/s HBM spec on a perfectly mixed 50/50 read/write stream.
//
// Ceiling characterization (10 structural variants, all 74.8-77.8us kernel):
// cp.async fills, __stcs/__ldcs streaming hints, 2- and 3-stage
// double-buffered pipelines, 512-thread blocks, warp-autonomous tiles with
// __syncwarp only, 4KB contiguous write bursts, grid-dimension reordering,
// and 256-bit st.global.v8.f32 stores were ALL neutral. The binding
// constraint is the HBM mixed-stream turnaround ceiling; no on-chip resource
// (issue<=16%, L2<=41%, L1<=44%, occ>=90%) approaches saturation. Both
// global phases are fully coalesced (512B/warp); both smem phases are
// bank-conflict-free (XOR swizzle col = wp ^ (cpl & 7): distinct col mod 8
// within every 8-lane LDS.128/STS.128 phase on both access patterns).
// Tail (ori_shape) fused into block 0 (a separate launch cost +3.6us).

#define N_ 16
#define C_ 64
#define HP_ 64
#define WP_ 64
#define CP_ 256            // C_*4
#define CPT_ 16            // cp rows per tile
#define THREADS 256
#define NDATA    (N_ * C_ * 256 * 256)     // data size in floats

__global__ __launch_bounds__(THREADS, 8)
void patch_permute_kernel(const float4* __restrict__ in, float4* __restrict__ out,
                          int tail_count) {
    __shared__ float4 tile[CPT_][WP_];   // 16 KB, XOR-swizzled

    const int cpt = blockIdx.x;    // 0..15  (cp in [cpt*16, cpt*16+16))
    const int hp  = blockIdx.y;    // 0..63
    const int n   = blockIdx.z;    // 0..15
    const int tid = threadIdx.x;

    // ---- fused tail write (ori_shape = 16,64,256,256), one block only ----
    if (cpt == 0 && hp == 0 && n == 0 && tid < 4 && tid < tail_count) {
        const float vals[4] = {16.0f, 64.0f, 256.0f, 256.0f};
        ((float*)out)[NDATA + tid] = vals[tid];
    }

    // ---- load: coalesced over wp (512B per warp), swizzled smem store ----
#pragma unroll
    for (int i = 0; i < (CPT_ * WP_) / THREADS; i++) {   // 4 iters
        int idx = i * THREADS + tid;
        int cpl = idx >> 6;          // 0..15
        int wp  = idx & 63;          // 0..63
        int cp  = cpt * CPT_ + cpl;
        int c   = cp >> 2;
        int pi  = cp & 3;
        int in_idx = ((n * C_ + c) * 256 + hp * 4 + pi) * WP_ + wp;
        tile[cpl][wp ^ (cpl & 7)] = in[in_idx];
    }
    __syncthreads();

    // ---- store: coalesced over cp (512B per warp), swizzled smem read ----
#pragma unroll
    for (int i = 0; i < (CPT_ * WP_) / THREADS; i++) {   // 4 iters
        int idx = i * THREADS + tid;
        int wp  = idx >> 4;          // 0..63
        int cpl = idx & 15;          // 0..15
        int cp  = cpt * CPT_ + cpl;
        int out_idx = ((n * WP_ + wp) * HP_ + hp) * CP_ + cp;
        out[out_idx] = tile[cpl][wp ^ (cpl & 7)];
    }
}

extern "C" void kernel_launch(void* const* d_in, const int* in_sizes, int n_in,
                              void* d_out, int out_size) {
    (void)in_sizes; (void)n_in;
    const float4* in  = (const float4*)d_in[0];
    float4*       out = (float4*)d_out;

    int tail_count = out_size > NDATA ? (out_size - NDATA) : 0;

    dim3 grid(CP_ / CPT_, HP_, N_);   // 16 x 64 x 16 = 16384 blocks
    patch_permute_kernel<<<grid, THREADS>>>(in, out, tail_count);
}

// round 16
// speedup vs baseline: 1.0051x; 1.0012x over previous
#include <cuda_runtime.h>
#include <cstdint>

// PatchEmbed permute: x[16,64,256,256] f32 -> out[16, 64*64, 64*4*4]
// out[n, wp, hp, c, pi, pj] = x[n, c, hp*4+pi, wp*4+pj]
// pj (4 floats) => float4 units. Per (n, hp): transpose M[cp=256][wp=64]
// of float4 where cp = c*4+pi.
//   input  f4 idx = ((n*64 + c)*256 + hp*4 + pi)*64 + wp   (contiguous in wp)
//   output f4 idx = ((n*64 + wp)*64 + hp)*256 + cp          (contiguous in cp)
//
// FINAL (converged): 256 threads, 16KB XOR-swizzled smem tile, plain
// LDG.128/STG.128, __launch_bounds__(256,8) -> 8 blocks x 8 warps =
// 64 warps/SM. Best measured: kernel 74.8us = 536.9MB/74.8us = 7.2 TB/s
// ~= 90% of the 8 TB/s HBM spec on a perfectly mixed 50/50 R/W stream;
// best totals 82.0 / 82.08us across independent runs.
//
// Ceiling characterization (10 structural variants, all 74.8-77.8us kernel):
// cp.async fills, __stcs/__ldcs streaming hints, 2- and 3-stage
// double-buffered pipelines, 512-thread blocks, warp-autonomous tiles with
// __syncwarp only, 4KB contiguous write bursts, grid-dimension reordering,
// and 256-bit st.global.v8.f32 stores were ALL neutral. Binding constraint:
// HBM mixed-stream turnaround ceiling (LTS cap is path-independent, so TMA
// stores would be equivalent). No on-chip resource (issue<=16%, L2<=41%,
// L1<=44%, occ>=90%) approaches saturation. Both global phases fully
// coalesced (512B/warp); both smem phases bank-conflict-free (XOR swizzle
// col = wp ^ (cpl & 7): distinct col mod 8 within every 8-lane
// LDS.128/STS.128 phase on both access patterns). Tail (ori_shape) fused
// into block 0 (a separate launch measured +3.6us of pure overhead).

#define N_ 16
#define C_ 64
#define HP_ 64
#define WP_ 64
#define CP_ 256            // C_*4
#define CPT_ 16            // cp rows per tile
#define THREADS 256
#define NDATA    (N_ * C_ * 256 * 256)     // data size in floats

__global__ __launch_bounds__(THREADS, 8)
void patch_permute_kernel(const float4* __restrict__ in, float4* __restrict__ out,
                          int tail_count) {
    __shared__ float4 tile[CPT_][WP_];   // 16 KB, XOR-swizzled

    const int cpt = blockIdx.x;    // 0..15  (cp in [cpt*16, cpt*16+16))
    const int hp  = blockIdx.y;    // 0..63
    const int n   = blockIdx.z;    // 0..15
    const int tid = threadIdx.x;

    // ---- fused tail write (ori_shape = 16,64,256,256), one block only ----
    if (cpt == 0 && hp == 0 && n == 0 && tid < 4 && tid < tail_count) {
        const float vals[4] = {16.0f, 64.0f, 256.0f, 256.0f};
        ((float*)out)[NDATA + tid] = vals[tid];
    }

    // ---- load: coalesced over wp (512B per warp), swizzled smem store ----
#pragma unroll
    for (int i = 0; i < (CPT_ * WP_) / THREADS; i++) {   // 4 iters
        int idx = i * THREADS + tid;
        int cpl = idx >> 6;          // 0..15
        int wp  = idx & 63;          // 0..63
        int cp  = cpt * CPT_ + cpl;
        int c   = cp >> 2;
        int pi  = cp & 3;
        int in_idx = ((n * C_ + c) * 256 + hp * 4 + pi) * WP_ + wp;
        tile[cpl][wp ^ (cpl & 7)] = in[in_idx];
    }
    __syncthreads();

    // ---- store: coalesced over cp (512B per warp), swizzled smem read ----
#pragma unroll
    for (int i = 0; i < (CPT_ * WP_) / THREADS; i++) {   // 4 iters
        int idx = i * THREADS + tid;
        int wp  = idx >> 4;          // 0..63
        int cpl = idx & 15;          // 0..15
        int cp  = cpt * CPT_ + cpl;
        int out_idx = ((n * WP_ + wp) * HP_ + hp) * CP_ + cp;
        out[out_idx] = tile[cpl][wp ^ (cpl & 7)];
    }
}

extern "C" void kernel_launch(void* const* d_in, const int* in_sizes, int n_in,
                              void* d_out, int out_size) {
    (void)in_sizes; (void)n_in;
    const float4* in  = (const float4*)d_in[0];
    float4*       out = (float4*)d_out;

    int tail_count = out_size > NDATA ? (out_size - NDATA) : 0;

    dim3 grid(CP_ / CPT_, HP_, N_);   // 16 x 64 x 16 = 16384 blocks
    patch_permute_kernel<<<grid, THREADS>>>(in, out, tail_count);
}